// round 16
// baseline (speedup 1.0000x reference)
#include <cuda_runtime.h>
#include <cstdint>

#define NB_GROUPS 8
#define TBL       32768          // 2^(P + N_GROUPS - 1)
#define BATCH     524288
#define N_TILES   (BATCH / 32)   // 16384 warp-tiles of 32 elements
#define GRID_MAP  148            // one 1024-thread block per SM, persistent
#define NTHREADS  1024

// Dynamic smem layout (bytes) -- per block
#define SM_TBL     0             // staged transposed tables g0..g3: 120 KB
#define SM_CARRY   122880        // 1792 B carry LUT
#define SM_NIB     124672        // 32 warps * 512 B nibble staging
#define SM_ADDR    141056        // 32 warps * 512 B (256 u16 addrs)
#define SMEM_TOTAL 157440

// Transposed table: [g][addr][p] -> each (g,addr) entry is one contiguous,
// 32B-aligned 8-float block. Only the USED prefix per group is populated:
// group g uses addr < 256<<g (addr = ga*2^g + carries).
#define USED_TOTAL 65280         // sum over g of 256<<g
__device__ float d_tpose[NB_GROUPS * TBL * 8];   // device-global scratch
__device__ unsigned int d_ticket;                // warp-tile work counter

// -------------------------------------------------------------------------
// Kernel 1: transpose only the USED entries of group_tables; reset ticket.
// -------------------------------------------------------------------------
__global__ __launch_bounds__(256) void transpose_kernel(const float* __restrict__ gt) {
    int idx = blockIdx.x * blockDim.x + threadIdx.x;   // 0 .. USED_TOTAL-1
    if (idx == 0) d_ticket = 0;                        // runs before mapper
    int k = (idx >> 8) + 1;                            // in [1, 256)
    int g = 31 - __clz(k);                             // group id, 0..7
    int a = idx - 256 * ((1 << g) - 1);                // addr within group
    float v[8];
#pragma unroll
    for (int p = 0; p < 8; ++p)
        v[p] = __ldg(&gt[((g * 8 + p) << 15) + a]);    // coalesced across lanes
    float4* dst = reinterpret_cast<float4*>(d_tpose) + ((size_t)((g << 15) | a) << 1);
    dst[0] = make_float4(v[0], v[1], v[2], v[3]);
    dst[1] = make_float4(v[4], v[5], v[6], v[7]);
}

// -------------------------------------------------------------------------
// Kernel 2: persistent mapper (R13 core; gathers are L2-only via __ldcg).
// Groups 0-3 gathered from SMEM, 4-7 from L2.
// -------------------------------------------------------------------------
__global__ __launch_bounds__(NTHREADS, 1) void mapper_kernel(
    const int4* __restrict__ bits4,   // (B, 64) int32 viewed as int4
    const int*  __restrict__ carry,   // (7, 256) int32 0/1
    float4*     __restrict__ out4)    // out viewed as float4
{
    extern __shared__ char smem[];
    uint8_t*  s_carry = (uint8_t*)(smem + SM_CARRY);

    const int t    = threadIdx.x;
    const int wid  = t >> 5;
    const int lane = t & 31;

    uint8_t*  s_nib  = (uint8_t*) (smem + SM_NIB)  + (wid << 9);
    uint16_t* s_addr = (uint16_t*)(smem + SM_ADDR + (wid << 9));

    // ---- stage carry LUT + transposed tables for groups 0..3 (120 KB) ----
    for (int i = t; i < 7 * 256; i += NTHREADS)
        s_carry[i] = (uint8_t)carry[i];
    {
        float4*       st4 = (float4*)(smem + SM_TBL);
        const float4* tp4 = (const float4*)d_tpose;
        const int pre4[4] = {0, 512, 1536, 3584};     // float4 prefix per group
#pragma unroll
        for (int g = 0; g < 4; ++g) {
            int cnt = 512 << g;                       // used entries * 2 float4
            for (int j = t; j < cnt; j += NTHREADS)
                st4[pre4[g] + j] = tp4[(g << 16) + j];
        }
    }
    __syncthreads();

    // ---- per-lane gather constants ----
    // L = i*32 + lane; h = lane&1; g = (lane>>1)&7; addr slot = sbase + 16*i
    const uint32_t gl    = (lane >> 1) & 7;
    const uint32_t hl    = lane & 1;
    const int      sbase = ((lane >> 4) << 3) + (int)gl;
    const bool     use_s = (gl < 4);
    const int pre_b[4] = {0, 8192, 24576, 57344};     // byte prefix per group
    const char* sgather = smem + SM_TBL + pre_b[gl & 3] + (hl << 4);
    const float4* __restrict__ tpb =
        reinterpret_cast<const float4*>(d_tpose) + ((gl << 16) | hl);

    for (;;) {
        // ---- pull next warp-tile (dynamic balancing) ----
        unsigned int tile;
        if (lane == 0) tile = atomicAdd(&d_ticket, 1u);
        tile = __shfl_sync(0xFFFFFFFFu, tile, 0);
        if (tile >= N_TILES) break;

        const int4* bp4 = bits4 + (size_t)tile * 512;   // 32 elems * 16 int4

        // ---- Phase A: 16 coalesced int4 loads -> nibble bytes in smem ----
#pragma unroll
        for (int i = 0; i < 16; ++i) {
            int L = i * 32 + lane;
            int4 v = __ldcs(&bp4[L]);
            s_nib[L] = (uint8_t)((v.x << 3) | (v.y << 2) | (v.z << 1) | v.w);
        }
        __syncwarp();

        // ---- Phase B: per-lane (element = lane) addresses + carry chain ----
        {
            uint4 nb = *reinterpret_cast<const uint4*>(&s_nib[lane * 16]);
            uint32_t wv[4] = {nb.x, nb.y, nb.z, nb.w};

            uint32_t pk[4];
            uint32_t c_run = 0;
#pragma unroll
            for (int g = 0; g < 8; ++g) {
                uint32_t wb = wv[g >> 1];
                uint32_t sh = (g & 1) * 16;
                uint32_t hi = (wb >> sh) & 0xFFu;        // nibble 2g   (p=0..3)
                uint32_t lo = (wb >> (sh + 8)) & 0xFFu;  // nibble 2g+1 (p=4..7)
                uint32_t ga = (hi << 4) | lo;
                uint32_t addr = (g == 0) ? ga : ((ga << g) | c_run);
                if ((g & 1) == 0) pk[g >> 1] = addr;
                else              pk[g >> 1] |= (addr << 16);
                if (g < 7)
                    c_run = (c_run << 1) | (uint32_t)s_carry[(g << 8) + ga];
            }
            *reinterpret_cast<uint4*>(&s_addr[lane * 8]) =
                make_uint4(pk[0], pk[1], pk[2], pk[3]);
        }
        __syncwarp();

        // ---- Phase C: hybrid gather (LDS g<4, L2-only LDG g>=4) + stores ----
        float4* __restrict__ ob = out4 + (size_t)tile * 512;
#pragma unroll
        for (int i = 0; i < 16; ++i) {
            uint32_t addr = s_addr[sbase + i * 16];
            float4 v;
            if (use_s)
                v = *reinterpret_cast<const float4*>(sgather + ((size_t)addr << 5));
            else
                v = __ldcg(&tpb[(size_t)addr << 1]);    // no L1 allocation
            __stcs(&ob[i * 32 + lane], v);              // evict-first
        }
        __syncwarp();   // protect s_addr/s_nib against next-iteration overwrite
    }
}

// -------------------------------------------------------------------------
extern "C" void kernel_launch(void* const* d_in, const int* in_sizes, int n_in,
                              void* d_out, int out_size) {
    const int4*  bits4 = (const int4*)d_in[0];       // (B, 64) int32
    const float* gt    = (const float*)d_in[1];      // (8, 8, 32768) f32
    const int*   carry = (const int*)d_in[2];        // (7, 256) int32
    float4*      out4  = (float4*)d_out;             // (B, 64) f32

    (void)in_sizes; (void)n_in; (void)out_size;

    static bool attr_set = false;
    if (!attr_set) {
        cudaFuncSetAttribute(mapper_kernel,
                             cudaFuncAttributeMaxDynamicSharedMemorySize,
                             SMEM_TOTAL);
        attr_set = true;
    }

    transpose_kernel<<<USED_TOTAL / 256, 256>>>(gt);     // used entries only
    mapper_kernel<<<GRID_MAP, NTHREADS, SMEM_TOTAL>>>(bits4, carry, out4);
}

// round 17
// speedup vs baseline: 1.0825x; 1.0825x over previous
#include <cuda_runtime.h>
#include <cstdint>

#define NB_GROUPS 8
#define TBL       32768          // 2^(P + N_GROUPS - 1)
#define BATCH     524288
#define N_TILES   (BATCH / 32)   // 16384 warp-tiles of 32 elements
#define GRID_MAP  148            // one 1024-thread block per SM, persistent
#define NTHREADS  1024

// Dynamic smem layout (bytes) -- per block
#define SM_TBL     0             // staged transposed tables g0..g3: 120 KB
#define SM_CARRY   122880        // 1792 B carry LUT
#define SM_NIB     124672        // 32 warps * 512 B nibble staging
#define SM_ADDR    141056        // 32 warps * 512 B (256 u16 addrs)
#define SMEM_TOTAL 157440

// Transposed table: [g][addr][p] -> each (g,addr) entry is one contiguous,
// 32B-aligned 8-float block. Only the USED prefix per group is populated:
// group g uses addr < 256<<g (addr = ga*2^g + carries).
#define USED_TOTAL 65280         // sum over g of 256<<g
__device__ float d_tpose[NB_GROUPS * TBL * 8];   // device-global scratch
__device__ unsigned int d_ticket;                // warp-tile work counter

// -------------------------------------------------------------------------
// Kernel 1: transpose only the USED entries of group_tables; reset ticket.
// -------------------------------------------------------------------------
__global__ __launch_bounds__(256) void transpose_kernel(const float* __restrict__ gt) {
    int idx = blockIdx.x * blockDim.x + threadIdx.x;   // 0 .. USED_TOTAL-1
    if (idx == 0) d_ticket = 0;                        // before this kernel ends
    int k = (idx >> 8) + 1;                            // in [1, 256)
    int g = 31 - __clz(k);                             // group id, 0..7
    int a = idx - 256 * ((1 << g) - 1);                // addr within group
    float v[8];
#pragma unroll
    for (int p = 0; p < 8; ++p)
        v[p] = __ldg(&gt[((g * 8 + p) << 15) + a]);    // coalesced across lanes
    float4* dst = reinterpret_cast<float4*>(d_tpose) + ((size_t)((g << 15) | a) << 1);
    dst[0] = make_float4(v[0], v[1], v[2], v[3]);
    dst[1] = make_float4(v[4], v[5], v[6], v[7]);
}

// -------------------------------------------------------------------------
// Kernel 2: persistent mapper (exact R13 core) launched with PDL.
// Carry staging runs BEFORE the grid dependency sync (overlaps transpose);
// everything touching d_tpose / d_ticket runs after it.
// -------------------------------------------------------------------------
__global__ __launch_bounds__(NTHREADS, 1) void mapper_kernel(
    const int4* __restrict__ bits4,   // (B, 64) int32 viewed as int4
    const int*  __restrict__ carry,   // (7, 256) int32 0/1
    float4*     __restrict__ out4)    // out viewed as float4
{
    extern __shared__ char smem[];
    uint8_t*  s_carry = (uint8_t*)(smem + SM_CARRY);

    const int t    = threadIdx.x;
    const int wid  = t >> 5;
    const int lane = t & 31;

    uint8_t*  s_nib  = (uint8_t*) (smem + SM_NIB)  + (wid << 9);
    uint16_t* s_addr = (uint16_t*)(smem + SM_ADDR + (wid << 9));

    // ---- pre-dependency work: carry LUT (reads only `carry` input) ----
    for (int i = t; i < 7 * 256; i += NTHREADS)
        s_carry[i] = (uint8_t)carry[i];

    // ---- wait for transpose kernel completion (PDL) ----
    cudaGridDependencySynchronize();

    // ---- stage transposed tables for groups 0..3 (120 KB, L2-hot) ----
    {
        float4*       st4 = (float4*)(smem + SM_TBL);
        const float4* tp4 = (const float4*)d_tpose;
        const int pre4[4] = {0, 512, 1536, 3584};     // float4 prefix per group
#pragma unroll
        for (int g = 0; g < 4; ++g) {
            int cnt = 512 << g;                       // used entries * 2 float4
            for (int j = t; j < cnt; j += NTHREADS)
                st4[pre4[g] + j] = tp4[(g << 16) + j];
        }
    }
    __syncthreads();

    // ---- per-lane gather constants ----
    // L = i*32 + lane; h = lane&1; g = (lane>>1)&7; addr slot = sbase + 16*i
    const uint32_t gl    = (lane >> 1) & 7;
    const uint32_t hl    = lane & 1;
    const int      sbase = ((lane >> 4) << 3) + (int)gl;
    const bool     use_s = (gl < 4);
    const int pre_b[4] = {0, 8192, 24576, 57344};     // byte prefix per group
    const char* sgather = smem + SM_TBL + pre_b[gl & 3] + (hl << 4);
    const float4* __restrict__ tpb =
        reinterpret_cast<const float4*>(d_tpose) + ((gl << 16) | hl);

    for (;;) {
        // ---- pull next warp-tile (dynamic balancing) ----
        unsigned int tile;
        if (lane == 0) tile = atomicAdd(&d_ticket, 1u);
        tile = __shfl_sync(0xFFFFFFFFu, tile, 0);
        if (tile >= N_TILES) break;

        const int4* bp4 = bits4 + (size_t)tile * 512;   // 32 elems * 16 int4

        // ---- Phase A: 16 coalesced int4 loads -> nibble bytes in smem ----
#pragma unroll
        for (int i = 0; i < 16; ++i) {
            int L = i * 32 + lane;
            int4 v = __ldcs(&bp4[L]);
            s_nib[L] = (uint8_t)((v.x << 3) | (v.y << 2) | (v.z << 1) | v.w);
        }
        __syncwarp();

        // ---- Phase B: per-lane (element = lane) addresses + carry chain ----
        {
            uint4 nb = *reinterpret_cast<const uint4*>(&s_nib[lane * 16]);
            uint32_t wv[4] = {nb.x, nb.y, nb.z, nb.w};

            uint32_t pk[4];
            uint32_t c_run = 0;
#pragma unroll
            for (int g = 0; g < 8; ++g) {
                uint32_t wb = wv[g >> 1];
                uint32_t sh = (g & 1) * 16;
                uint32_t hi = (wb >> sh) & 0xFFu;        // nibble 2g   (p=0..3)
                uint32_t lo = (wb >> (sh + 8)) & 0xFFu;  // nibble 2g+1 (p=4..7)
                uint32_t ga = (hi << 4) | lo;
                uint32_t addr = (g == 0) ? ga : ((ga << g) | c_run);
                if ((g & 1) == 0) pk[g >> 1] = addr;
                else              pk[g >> 1] |= (addr << 16);
                if (g < 7)
                    c_run = (c_run << 1) | (uint32_t)s_carry[(g << 8) + ga];
            }
            *reinterpret_cast<uint4*>(&s_addr[lane * 8]) =
                make_uint4(pk[0], pk[1], pk[2], pk[3]);
        }
        __syncwarp();

        // ---- Phase C: hybrid gather (LDS g<4, LDG g>=4) + streaming stores ----
        float4* __restrict__ ob = out4 + (size_t)tile * 512;
#pragma unroll
        for (int i = 0; i < 16; ++i) {
            uint32_t addr = s_addr[sbase + i * 16];
            float4 v;
            if (use_s)
                v = *reinterpret_cast<const float4*>(sgather + ((size_t)addr << 5));
            else
                v = __ldg(&tpb[(size_t)addr << 1]);     // L1-cached (R16: ldcg hurt)
            __stcs(&ob[i * 32 + lane], v);              // evict-first
        }
        __syncwarp();   // protect s_addr/s_nib against next-iteration overwrite
    }
}

// -------------------------------------------------------------------------
extern "C" void kernel_launch(void* const* d_in, const int* in_sizes, int n_in,
                              void* d_out, int out_size) {
    const int4*  bits4 = (const int4*)d_in[0];       // (B, 64) int32
    const float* gt    = (const float*)d_in[1];      // (8, 8, 32768) f32
    const int*   carry = (const int*)d_in[2];        // (7, 256) int32
    float4*      out4  = (float4*)d_out;             // (B, 64) f32

    (void)in_sizes; (void)n_in; (void)out_size;

    static bool attr_set = false;
    if (!attr_set) {
        cudaFuncSetAttribute(mapper_kernel,
                             cudaFuncAttributeMaxDynamicSharedMemorySize,
                             SMEM_TOTAL);
        attr_set = true;
    }

    transpose_kernel<<<USED_TOTAL / 256, 256>>>(gt);     // used entries only

    // PDL launch: mapper starts while transpose runs; device-side
    // cudaGridDependencySynchronize() enforces the data dependency.
    cudaLaunchConfig_t cfg = {};
    cfg.gridDim          = dim3(GRID_MAP, 1, 1);
    cfg.blockDim         = dim3(NTHREADS, 1, 1);
    cfg.dynamicSmemBytes = SMEM_TOTAL;
    cudaLaunchAttribute attrs[1];
    attrs[0].id = cudaLaunchAttributeProgrammaticStreamSerialization;
    attrs[0].val.programmaticStreamSerializationAllowed = 1;
    cfg.attrs    = attrs;
    cfg.numAttrs = 1;
    cudaLaunchKernelEx(&cfg, mapper_kernel, bits4, carry, out4);
}